// round 4
// baseline (speedup 1.0000x reference)
#include <cuda_runtime.h>
#include <math_constants.h>
#include <stdint.h>

#define N_BINS 15
#define C_DIM  100
#define RPI    4            // rows per warp iteration
#define FULL   0xffffffffu

__device__ float  g_cnt[N_BINS];
__device__ double g_conf[N_BINS];
__device__ float  g_accs[N_BINS];
__device__ int    g_is64;   // 1 if labels are int64, 0 if int32

// Zero accumulators AND detect label dtype (odd int32 words all zero => int64).
__global__ void ece_zero_kernel(const int* __restrict__ labels32, int n) {
    __shared__ int s_any;
    if (threadIdx.x == 0) s_any = 0;
    __syncthreads();

    if (threadIdx.x < N_BINS) {
        g_cnt[threadIdx.x]  = 0.0f;
        g_conf[threadIdx.x] = 0.0;
        g_accs[threadIdx.x] = 0.0f;
    }

    int any = 0;
    for (int idx = 1 + 2 * threadIdx.x; idx < n; idx += 2 * blockDim.x) {
        if (labels32[idx] != 0) { any = 1; break; }
    }
    if (any) atomicOr(&s_any, 1);
    __syncthreads();
    if (threadIdx.x == 0) g_is64 = (s_any == 0) ? 1 : 0;
}

// Order-preserving float -> u32 map (max over u32 == max over float)
__device__ __forceinline__ unsigned fmap(float f) {
    unsigned b = __float_as_uint(f);
    return ((int)b >= 0) ? (b | 0x80000000u) : ~b;
}

__global__ void __launch_bounds__(256) ece_accum_kernel(
    const float* __restrict__ logits,
    const void*  __restrict__ labels_raw,
    int n, int vec_ok)
{
    __shared__ float  s_cnt[N_BINS];
    __shared__ double s_conf[N_BINS];
    __shared__ float  s_acc[N_BINS];
    if (threadIdx.x < N_BINS) {
        s_cnt[threadIdx.x]  = 0.0f;
        s_conf[threadIdx.x] = 0.0;
        s_acc[threadIdx.x]  = 0.0f;
    }
    __syncthreads();

    const int is64 = g_is64;
    const int* __restrict__       lab32 = (const int*)labels_raw;
    const long long* __restrict__ lab64 = (const long long*)labels_raw;

    const int lane   = threadIdx.x & 31;
    const int warp   = (int)((blockIdx.x * blockDim.x + threadIdx.x) >> 5);
    const int nwarps = (int)((gridDim.x * blockDim.x) >> 5);

    for (int row0 = warp * RPI; row0 < n; row0 += nwarps * RPI) {
        const int nvalid = min(RPI, n - row0);

        // Prefetch labels for the RPI rows into lanes 25..25+RPI-1
        // (issued alongside the logit loads -> off the critical path).
        int labv = 0;
        if (lane >= 25 && lane < 25 + nvalid) {
            int r = row0 + (lane - 25);
            labv = is64 ? (int)lab64[r] : lab32[r];
        }

        float4 v[RPI];
        if (vec_ok && lane < 25) {
            const float4* bp = reinterpret_cast<const float4*>(logits)
                             + (size_t)row0 * 25 + lane;
            #pragma unroll
            for (int k = 0; k < RPI; k++)
                if (k < nvalid) v[k] = bp[k * 25];   // independent: MLP = RPI
        }

        #pragma unroll
        for (int k = 0; k < RPI; k++) {
            if (k >= nvalid) break;

            float m  = -CUDART_INF_F;
            int   mi = 0x7fffffff;
            unsigned mu = 0u;

            if (vec_ok) {
                if (lane < 25) {
                    int base = lane * 4;
                    m = v[k].x; mi = base;
                    if (v[k].y > m) { m = v[k].y; mi = base + 1; }
                    if (v[k].z > m) { m = v[k].z; mi = base + 2; }
                    if (v[k].w > m) { m = v[k].w; mi = base + 3; }
                    mu = fmap(m);
                }
            } else {
                const float* rowp = logits + (size_t)(row0 + k) * C_DIM;
                #pragma unroll
                for (int j = 0; j < 4; j++) {
                    int c = lane + j * 32;
                    if (c < C_DIM) {
                        float x = rowp[c];
                        if (x > m) { m = x; mi = c; }
                    }
                }
                mu = fmap(m);
            }

            // Warp argmax: redux on mapped value, ballot picks lowest lane
            // (== lowest index in the float4 layout -> jnp.argmax semantics).
            unsigned maxu = __reduce_max_sync(FULL, mu);
            unsigned wm   = __ballot_sync(FULL, mu == maxu);
            int src = __ffs(wm) - 1;
            float mm  = __shfl_sync(FULL, m,  src);
            int   ami = __shfl_sync(FULL, mi, src);
            int   lab = __shfl_sync(FULL, labv, 25 + k);

            if (lane == 0) {
                // sigmoid monotone: conf = sigmoid(max logit)
                float conf = 1.0f / (1.0f + __expf(-mm));
                // searchsorted(linspace(0,1,16), conf, 'left') - 1, clipped
                int bin = (int)ceilf(conf * 15.0f) - 1;
                bin = bin < 0 ? 0 : (bin > N_BINS - 1 ? N_BINS - 1 : bin);

                atomicAdd(&s_cnt[bin], 1.0f);
                atomicAdd(&s_conf[bin], (double)conf);
                atomicAdd(&s_acc[bin], (ami == lab) ? 1.0f : 0.0f);
            }
        }
    }

    __syncthreads();
    if (threadIdx.x < N_BINS) {
        float c = s_cnt[threadIdx.x];
        if (c != 0.0f) {
            atomicAdd(&g_cnt[threadIdx.x],  c);
            atomicAdd(&g_conf[threadIdx.x], s_conf[threadIdx.x]);
            atomicAdd(&g_accs[threadIdx.x], s_acc[threadIdx.x]);
        }
    }
}

__global__ void ece_final_kernel(float* __restrict__ out, float inv_n) {
    if (threadIdx.x == 0 && blockIdx.x == 0) {
        float ece = 0.0f;
        #pragma unroll
        for (int b = 0; b < N_BINS; b++) {
            float cnt = g_cnt[b];
            if (cnt > 0.0f) {
                float avg_conf = (float)g_conf[b] / cnt;
                float avg_acc  = g_accs[b] / cnt;
                ece += (avg_conf - avg_acc) * (cnt * inv_n);
            }
        }
        out[0] = ece;
    }
}

extern "C" void kernel_launch(void* const* d_in, const int* in_sizes, int n_in,
                              void* d_out, int out_size) {
    // Resolve input order by element count (logits = C_DIM x labels count).
    long long s0 = in_sizes[0], s1 = in_sizes[1];
    int logits_idx = (s0 > s1) ? 0 : 1;
    int labels_idx = 1 - logits_idx;

    const float* logits     = (const float*)d_in[logits_idx];
    const void*  labels_raw = d_in[labels_idx];
    int n = (int)((s0 < s1) ? s0 : s1);
    float* out = (float*)d_out;

    int vec_ok = ((uintptr_t)logits & 15) == 0 ? 1 : 0;

    ece_zero_kernel<<<1, 256>>>((const int*)labels_raw, n);

    const int threads = 256;
    const int blocks  = 2368;
    ece_accum_kernel<<<blocks, threads>>>(logits, labels_raw, n, vec_ok);

    ece_final_kernel<<<1, 32>>>(out, 1.0f / (float)n);
}